// round 3
// baseline (speedup 1.0000x reference)
#include <cuda_runtime.h>
#include <cstdint>

// Problem constants (BSZ=1)
#define SEQn   2048
#define Hn     128
#define DNOPE  128
#define DROPE  64
#define VQK    48   // 192/4 float4 per output row
#define VKV    64   // 256/4 float4 per kv row

// Region sizes in float4 units
#define NA  8388608    // q_nope copy:       262144 rows x 32
#define NB  4194304    // q rope:            262144 rows x 16
#define NC  16777216   // kv copy:           524288 rows x 32
#define ND  4194304    // k_pe rope bcast:   262144 rows x 16
#define NE  4194304    // zero fill:         262144 rows x 16

// CTA partition (proportional to DRAM bytes); total 1184 = 148 SMs x 8
#define BA  296
#define BB  148
#define BC  592
#define BD  74
#define BE  74
#define NBLOCKS (BA + BB + BC + BD + BE)

__global__ void __launch_bounds__(256)
fused_mla_rope_kernel(const float4* __restrict__ q,
                      const float4* __restrict__ kv,
                      const float4* __restrict__ k_pe,
                      const float*  __restrict__ cos_t,
                      const float*  __restrict__ sin_t,
                      const int*    __restrict__ pos,
                      float4* __restrict__ out_q,
                      float4* __restrict__ out_kv)
{
    const int b   = blockIdx.x;
    const int tid = threadIdx.x;

    if (b < BA) {
        // ---- Region A: q_nope pure copy (rows of 48, first 32 v4) ----
        const int stride = BA * 256;
        #pragma unroll 4
        for (int i = b * 256 + tid; i < NA; i += stride) {
            int row = i >> 5, c = i & 31;
            int idx = row * VQK + c;
            float4 v = __ldcs(&q[idx]);
            __stcs(&out_q[idx], v);
        }
    } else if (b < BA + BB) {
        // ---- Region B: q rope (16 v4 per row) ----
        const int lb = b - BA;
        const int stride = BB * 256;
        #pragma unroll 4
        for (int i = lb * 256 + tid; i < NB; i += stride) {
            int row = i >> 4, c = i & 15;           // row = s*128 + h
            int s = row >> 7;
            int p = __ldg(&pos[s]);
            int pc  = (c < 8) ? c + 8 : c - 8;
            float sgn = (c < 8) ? -1.0f : 1.0f;
            int base = row * VQK + 32;

            float4 x  = __ldg(&q[base + c]);
            float4 xp = __ldg(&q[base + pc]);
            float4 cc = __ldg((const float4*)(cos_t + p * DROPE) + c);
            float4 ss = __ldg((const float4*)(sin_t + p * DROPE) + c);

            float4 r;
            r.x = fmaf(sgn * xp.x, ss.x, x.x * cc.x);
            r.y = fmaf(sgn * xp.y, ss.y, x.y * cc.y);
            r.z = fmaf(sgn * xp.z, ss.z, x.z * cc.z);
            r.w = fmaf(sgn * xp.w, ss.w, x.w * cc.w);
            __stcs(&out_q[base + c], r);
        }
    } else if (b < BA + BB + BC) {
        // ---- Region C: kv copy -> res_kv [rr][0:32] ----
        const int lb = b - (BA + BB);
        const int stride = BC * 256;
        #pragma unroll 4
        for (int i = lb * 256 + tid; i < NC; i += stride) {
            int rr = i >> 5, c = i & 31;            // rr = (s*2+slot)*128 + h
            int h = rr & 127;
            int t = rr >> 7;
            int slot = t & 1, s = t >> 1;
            int src = ((s << 7) + h) * VKV + (slot << 5) + c;
            float4 v = __ldcs(&kv[src]);
            __stcs(&out_kv[rr * VQK + c], v);
        }
    } else if (b < BA + BB + BC + BD) {
        // ---- Region D: rope(k_pe[s]) broadcast -> res_kv slot0 [128:192] ----
        const int lb = b - (BA + BB + BC);
        const int stride = BD * 256;
        #pragma unroll 4
        for (int i = lb * 256 + tid; i < ND; i += stride) {
            int row = i >> 4, c = i & 15;           // row = s*128 + h
            int s = row >> 7, h = row & 127;
            int p = __ldg(&pos[s]);
            int pc  = (c < 8) ? c + 8 : c - 8;
            float sgn = (c < 8) ? -1.0f : 1.0f;

            const float4* kp = k_pe + s * (DROPE / 4);
            float4 x  = __ldg(&kp[c]);
            float4 xp = __ldg(&kp[pc]);
            float4 cc = __ldg((const float4*)(cos_t + p * DROPE) + c);
            float4 ss = __ldg((const float4*)(sin_t + p * DROPE) + c);

            float4 r;
            r.x = fmaf(sgn * xp.x, ss.x, x.x * cc.x);
            r.y = fmaf(sgn * xp.y, ss.y, x.y * cc.y);
            r.z = fmaf(sgn * xp.z, ss.z, x.z * cc.z);
            r.w = fmaf(sgn * xp.w, ss.w, x.w * cc.w);

            int dst = ((s << 8) + h) * VQK + 32 + c;   // rw = s*256 + h
            __stcs(&out_kv[dst], r);
        }
    } else {
        // ---- Region E: zero fill -> res_kv slot1 [128:192] ----
        const int lb = b - (BA + BB + BC + BD);
        const int stride = BE * 256;
        const float4 z = make_float4(0.f, 0.f, 0.f, 0.f);
        #pragma unroll 4
        for (int i = lb * 256 + tid; i < NE; i += stride) {
            int row = i >> 4, c = i & 15;
            int s = row >> 7, h = row & 127;
            int dst = ((s << 8) + 128 + h) * VQK + 32 + c;  // rw = s*256 + 128 + h
            __stcs(&out_kv[dst], z);
        }
    }
}

extern "C" void kernel_launch(void* const* d_in, const int* in_sizes, int n_in,
                              void* d_out, int out_size)
{
    const float4* q     = (const float4*)d_in[0];
    const float4* kv    = (const float4*)d_in[1];
    const float4* k_pe  = (const float4*)d_in[2];
    const float*  cos_t = (const float*)d_in[3];
    const float*  sin_t = (const float*)d_in[4];
    const int*    pos   = (const int*)d_in[5];

    float4* out_q  = (float4*)d_out;
    float4* out_kv = out_q + (long long)SEQn * Hn * VQK;   // + 12,582,912

    fused_mla_rope_kernel<<<NBLOCKS, 256>>>(q, kv, k_pe, cos_t, sin_t, pos,
                                            out_q, out_kv);
}

// round 4
// speedup vs baseline: 1.4018x; 1.4018x over previous
#include <cuda_runtime.h>
#include <cstdint>

// Problem constants (BSZ=1)
#define DROPE  64
#define VQK    48   // 192/4 float4 per output row
#define VKV    64   // 256/4 float4 per kv row

// Block-range partition: each block handles 256 contiguous elements of ONE region.
#define BLK_A  32768u   // q_nope copy:  8388608 el
#define BLK_B  16384u   // q rope:       4194304 el
#define BLK_C  65536u   // kv copy:     16777216 el
#define BLK_D  16384u   // k_pe rope:    4194304 el
#define BLK_E  16384u   // zero fill:    4194304 el
#define NBLOCKS (BLK_A + BLK_B + BLK_C + BLK_D + BLK_E)   // 147456

__global__ void __launch_bounds__(256)
fused_mla_rope_kernel(const float4* __restrict__ q,
                      const float4* __restrict__ kv,
                      const float4* __restrict__ k_pe,
                      const float*  __restrict__ cos_t,
                      const float*  __restrict__ sin_t,
                      const int*    __restrict__ pos,
                      float4* __restrict__ out_q,
                      float4* __restrict__ out_kv)
{
    const unsigned b   = blockIdx.x;
    const unsigned tid = threadIdx.x;

    if (b < BLK_A) {
        // ---- A: q_nope copy. Element i -> row=i>>5 (of 262144), c=i&31 ----
        unsigned i = b * 256u + tid;
        unsigned row = i >> 5, c = i & 31;
        unsigned idx = row * VQK + c;
        out_q[idx] = __ldg(&q[idx]);
    } else if (b < BLK_A + BLK_B) {
        // ---- B: q rope. Element i -> row=i>>4, c=i&15 (v4 within rope seg) ----
        unsigned i = (b - BLK_A) * 256u + tid;
        unsigned row = i >> 4, c = i & 15;      // row = s*128 + h
        unsigned s = row >> 7;
        int p = __ldg(&pos[s]);
        unsigned pc = (c < 8) ? c + 8 : c - 8;
        float sgn = (c < 8) ? -1.0f : 1.0f;
        unsigned base = row * VQK + 32;

        float4 x  = __ldg(&q[base + c]);
        float4 xp = __ldg(&q[base + pc]);
        float4 cc = __ldg((const float4*)(cos_t + p * DROPE) + c);
        float4 ss = __ldg((const float4*)(sin_t + p * DROPE) + c);

        float4 r;
        r.x = fmaf(sgn * xp.x, ss.x, x.x * cc.x);
        r.y = fmaf(sgn * xp.y, ss.y, x.y * cc.y);
        r.z = fmaf(sgn * xp.z, ss.z, x.z * cc.z);
        r.w = fmaf(sgn * xp.w, ss.w, x.w * cc.w);
        out_q[base + c] = r;
    } else if (b < BLK_A + BLK_B + BLK_C) {
        // ---- C: kv copy -> res_kv[rr][0:32] ----
        unsigned i = (b - (BLK_A + BLK_B)) * 256u + tid;
        unsigned rr = i >> 5, c = i & 31;       // rr = (s*2+slot)*128 + h
        unsigned h = rr & 127;
        unsigned t = rr >> 7;
        unsigned slot = t & 1, s = t >> 1;
        unsigned src = ((s << 7) + h) * VKV + (slot << 5) + c;
        out_kv[rr * VQK + c] = __ldg(&kv[src]);
    } else if (b < BLK_A + BLK_B + BLK_C + BLK_D) {
        // ---- D: rope(k_pe[s]) broadcast -> res_kv slot0 [cols 128:192] ----
        unsigned i = (b - (BLK_A + BLK_B + BLK_C)) * 256u + tid;
        unsigned row = i >> 4, c = i & 15;      // row = s*128 + h
        unsigned s = row >> 7, h = row & 127;
        int p = __ldg(&pos[s]);
        unsigned pc = (c < 8) ? c + 8 : c - 8;
        float sgn = (c < 8) ? -1.0f : 1.0f;

        const float4* kp = k_pe + s * (DROPE / 4);
        float4 x  = __ldg(&kp[c]);
        float4 xp = __ldg(&kp[pc]);
        float4 cc = __ldg((const float4*)(cos_t + p * DROPE) + c);
        float4 ss = __ldg((const float4*)(sin_t + p * DROPE) + c);

        float4 r;
        r.x = fmaf(sgn * xp.x, ss.x, x.x * cc.x);
        r.y = fmaf(sgn * xp.y, ss.y, x.y * cc.y);
        r.z = fmaf(sgn * xp.z, ss.z, x.z * cc.z);
        r.w = fmaf(sgn * xp.w, ss.w, x.w * cc.w);

        unsigned dst = ((s << 8) + h) * VQK + 32 + c;       // rw = s*256 + h
        out_kv[dst] = r;
    } else {
        // ---- E: zero fill -> res_kv slot1 [cols 128:192] ----
        unsigned i = (b - (BLK_A + BLK_B + BLK_C + BLK_D)) * 256u + tid;
        unsigned row = i >> 4, c = i & 15;
        unsigned s = row >> 7, h = row & 127;
        unsigned dst = ((s << 8) + 128 + h) * VQK + 32 + c; // rw = s*256 + 128 + h
        out_kv[dst] = make_float4(0.f, 0.f, 0.f, 0.f);
    }
}

extern "C" void kernel_launch(void* const* d_in, const int* in_sizes, int n_in,
                              void* d_out, int out_size)
{
    const float4* q     = (const float4*)d_in[0];
    const float4* kv    = (const float4*)d_in[1];
    const float4* k_pe  = (const float4*)d_in[2];
    const float*  cos_t = (const float*)d_in[3];
    const float*  sin_t = (const float*)d_in[4];
    const int*    pos   = (const int*)d_in[5];

    float4* out_q  = (float4*)d_out;
    float4* out_kv = out_q + (long long)2048 * 128 * VQK;   // + 12,582,912

    fused_mla_rope_kernel<<<NBLOCKS, 256>>>(q, kv, k_pe, cos_t, sin_t, pos,
                                            out_q, out_kv);
}

// round 5
// speedup vs baseline: 1.5009x; 1.0706x over previous
#include <cuda_runtime.h>
#include <cstdint>

// Problem constants (BSZ=1)
#define DROPE  64
#define VQK    48   // 192/4 float4 per output row
#define VKV    64   // 256/4 float4 per kv row

// Each block handles 512 contiguous elements of ONE region (2 per thread).
#define BLK_A  16384u   // q_nope copy:  8388608 el
#define BLK_B   8192u   // q rope:       4194304 el
#define BLK_C  32768u   // kv copy:     16777216 el
#define BLK_D   8192u   // k_pe rope:    4194304 el
#define BLK_E   8192u   // zero fill:    4194304 el
#define NBLOCKS (BLK_A + BLK_B + BLK_C + BLK_D + BLK_E)   // 73728

__device__ __forceinline__ float4 rope4(float4 x, float4 xp, float4 cc, float4 ss, float sgn)
{
    float4 r;
    r.x = fmaf(sgn * xp.x, ss.x, x.x * cc.x);
    r.y = fmaf(sgn * xp.y, ss.y, x.y * cc.y);
    r.z = fmaf(sgn * xp.z, ss.z, x.z * cc.z);
    r.w = fmaf(sgn * xp.w, ss.w, x.w * cc.w);
    return r;
}

__global__ void __launch_bounds__(256)
fused_mla_rope_kernel(const float4* __restrict__ q,
                      const float4* __restrict__ kv,
                      const float4* __restrict__ k_pe,
                      const float*  __restrict__ cos_t,
                      const float*  __restrict__ sin_t,
                      const int*    __restrict__ pos,
                      float4* __restrict__ out_q,
                      float4* __restrict__ out_kv)
{
    const unsigned b   = blockIdx.x;
    const unsigned tid = threadIdx.x;

    if (b < BLK_A) {
        // ---- A: q_nope copy ----
        unsigned i0 = b * 512u + tid;
        unsigned i1 = i0 + 256u;
        unsigned idx0 = (i0 >> 5) * VQK + (i0 & 31);
        unsigned idx1 = (i1 >> 5) * VQK + (i1 & 31);
        float4 v0 = __ldg(&q[idx0]);
        float4 v1 = __ldg(&q[idx1]);
        out_q[idx0] = v0;
        out_q[idx1] = v1;
    } else if (b < BLK_A + BLK_B) {
        // ---- B: q rope ----
        unsigned base_i = (b - BLK_A) * 512u + tid;
        #pragma unroll
        for (int u = 0; u < 2; u++) {
            unsigned i = base_i + u * 256u;
            unsigned row = i >> 4, c = i & 15;      // row = s*128 + h
            unsigned s = row >> 7;
            int p = __ldg(&pos[s]);
            unsigned pc = (c < 8) ? c + 8 : c - 8;
            float sgn = (c < 8) ? -1.0f : 1.0f;
            unsigned base = row * VQK + 32;

            float4 x  = __ldg(&q[base + c]);
            float4 xp = __ldg(&q[base + pc]);
            float4 cc = __ldg((const float4*)(cos_t + p * DROPE) + c);
            float4 ss = __ldg((const float4*)(sin_t + p * DROPE) + c);
            out_q[base + c] = rope4(x, xp, cc, ss, sgn);
        }
    } else if (b < BLK_A + BLK_B + BLK_C) {
        // ---- C: kv copy -> res_kv[rr][0:32] ----
        unsigned i0 = (b - (BLK_A + BLK_B)) * 512u + tid;
        unsigned i1 = i0 + 256u;

        unsigned rr0 = i0 >> 5, c0 = i0 & 31;
        unsigned h0 = rr0 & 127, t0 = rr0 >> 7;
        unsigned src0 = (((t0 >> 1) << 7) + h0) * VKV + ((t0 & 1) << 5) + c0;

        unsigned rr1 = i1 >> 5, c1 = i1 & 31;
        unsigned h1 = rr1 & 127, t1 = rr1 >> 7;
        unsigned src1 = (((t1 >> 1) << 7) + h1) * VKV + ((t1 & 1) << 5) + c1;

        float4 v0 = __ldcs(&kv[src0]);
        float4 v1 = __ldcs(&kv[src1]);
        __stcs(&out_kv[rr0 * VQK + c0], v0);
        __stcs(&out_kv[rr1 * VQK + c1], v1);
    } else if (b < BLK_A + BLK_B + BLK_C + BLK_D) {
        // ---- D: rope(k_pe[s]) broadcast -> res_kv slot0 [cols 128:192] ----
        unsigned base_i = (b - (BLK_A + BLK_B + BLK_C)) * 512u + tid;
        #pragma unroll
        for (int u = 0; u < 2; u++) {
            unsigned i = base_i + u * 256u;
            unsigned row = i >> 4, c = i & 15;      // row = s*128 + h
            unsigned s = row >> 7, h = row & 127;
            int p = __ldg(&pos[s]);
            unsigned pc = (c < 8) ? c + 8 : c - 8;
            float sgn = (c < 8) ? -1.0f : 1.0f;

            const float4* kp = k_pe + s * (DROPE / 4);
            float4 x  = __ldg(&kp[c]);
            float4 xp = __ldg(&kp[pc]);
            float4 cc = __ldg((const float4*)(cos_t + p * DROPE) + c);
            float4 ss = __ldg((const float4*)(sin_t + p * DROPE) + c);

            unsigned dst = ((s << 8) + h) * VQK + 32 + c;   // rw = s*256 + h
            out_kv[dst] = rope4(x, xp, cc, ss, sgn);
        }
    } else {
        // ---- E: zero fill -> res_kv slot1 [cols 128:192] ----
        unsigned base_i = (b - (BLK_A + BLK_B + BLK_C + BLK_D)) * 512u + tid;
        const float4 z = make_float4(0.f, 0.f, 0.f, 0.f);
        #pragma unroll
        for (int u = 0; u < 2; u++) {
            unsigned i = base_i + u * 256u;
            unsigned row = i >> 4, c = i & 15;
            unsigned s = row >> 7, h = row & 127;
            unsigned dst = ((s << 8) + 128 + h) * VQK + 32 + c;
            __stcs(&out_kv[dst], z);
        }
    }
}

extern "C" void kernel_launch(void* const* d_in, const int* in_sizes, int n_in,
                              void* d_out, int out_size)
{
    const float4* q     = (const float4*)d_in[0];
    const float4* kv    = (const float4*)d_in[1];
    const float4* k_pe  = (const float4*)d_in[2];
    const float*  cos_t = (const float*)d_in[3];
    const float*  sin_t = (const float*)d_in[4];
    const int*    pos   = (const int*)d_in[5];

    float4* out_q  = (float4*)d_out;
    float4* out_kv = out_q + (long long)2048 * 128 * VQK;   // + 12,582,912

    fused_mla_rope_kernel<<<NBLOCKS, 256>>>(q, kv, k_pe, cos_t, sin_t, pos,
                                            out_q, out_kv);
}

// round 6
// speedup vs baseline: 1.5691x; 1.0454x over previous
#include <cuda_runtime.h>
#include <cstdint>

// Problem constants (BSZ=1)
#define DROPE  64
#define VQK    48   // 192/4 float4 per output row
#define VKV    64   // 256/4 float4 per kv row

// Each block handles 1024 contiguous elements of ONE region (4 per thread).
#define BLK_A   8192u   // q_nope copy:  8388608 el
#define BLK_B   4096u   // q rope:       4194304 el
#define BLK_C  16384u   // kv copy:     16777216 el
#define BLK_D   4096u   // k_pe rope:    4194304 el
#define BLK_E   4096u   // zero fill:    4194304 el
#define NBLOCKS (BLK_A + BLK_B + BLK_C + BLK_D + BLK_E)   // 36864

__device__ __forceinline__ float4 rope4(float4 x, float4 xp, float4 cc, float4 ss, float sgn)
{
    float4 r;
    r.x = fmaf(sgn * xp.x, ss.x, x.x * cc.x);
    r.y = fmaf(sgn * xp.y, ss.y, x.y * cc.y);
    r.z = fmaf(sgn * xp.z, ss.z, x.z * cc.z);
    r.w = fmaf(sgn * xp.w, ss.w, x.w * cc.w);
    return r;
}

__global__ void __launch_bounds__(256)
fused_mla_rope_kernel(const float4* __restrict__ q,
                      const float4* __restrict__ kv,
                      const float4* __restrict__ k_pe,
                      const float*  __restrict__ cos_t,
                      const float*  __restrict__ sin_t,
                      const int*    __restrict__ pos,
                      float4* __restrict__ out_q,
                      float4* __restrict__ out_kv)
{
    const unsigned b   = blockIdx.x;
    const unsigned tid = threadIdx.x;

    if (b < BLK_A) {
        // ---- A: q_nope copy (4x ILP) ----
        unsigned i0 = b * 1024u + tid;
        unsigned idx[4];
        float4 v[4];
        #pragma unroll
        for (int u = 0; u < 4; u++) {
            unsigned i = i0 + u * 256u;
            idx[u] = (i >> 5) * VQK + (i & 31);
        }
        #pragma unroll
        for (int u = 0; u < 4; u++) v[u] = __ldcs(&q[idx[u]]);
        #pragma unroll
        for (int u = 0; u < 4; u++) __stcs(&out_q[idx[u]], v[u]);
    } else if (b < BLK_A + BLK_B) {
        // ---- B: q rope (4x ILP) ----
        unsigned base_i = (b - BLK_A) * 1024u + tid;
        #pragma unroll
        for (int u = 0; u < 4; u++) {
            unsigned i = base_i + u * 256u;
            unsigned row = i >> 4, c = i & 15;      // row = s*128 + h
            unsigned s = row >> 7;
            int p = __ldg(&pos[s]);
            unsigned pc = (c < 8) ? c + 8 : c - 8;
            float sgn = (c < 8) ? -1.0f : 1.0f;
            unsigned base = row * VQK + 32;

            float4 x  = __ldcs(&q[base + c]);
            float4 xp = __ldg(&q[base + pc]);
            float4 cc = __ldg((const float4*)(cos_t + p * DROPE) + c);
            float4 ss = __ldg((const float4*)(sin_t + p * DROPE) + c);
            __stcs(&out_q[base + c], rope4(x, xp, cc, ss, sgn));
        }
    } else if (b < BLK_A + BLK_B + BLK_C) {
        // ---- C: kv copy -> res_kv[rr][0:32] (4x ILP) ----
        unsigned i0 = (b - (BLK_A + BLK_B)) * 1024u + tid;
        unsigned src[4], dst[4];
        float4 v[4];
        #pragma unroll
        for (int u = 0; u < 4; u++) {
            unsigned i = i0 + u * 256u;
            unsigned rr = i >> 5, c = i & 31;       // rr = (s*2+slot)*128 + h
            unsigned h = rr & 127, t = rr >> 7;
            src[u] = (((t >> 1) << 7) + h) * VKV + ((t & 1) << 5) + c;
            dst[u] = rr * VQK + c;
        }
        #pragma unroll
        for (int u = 0; u < 4; u++) v[u] = __ldcs(&kv[src[u]]);
        #pragma unroll
        for (int u = 0; u < 4; u++) __stcs(&out_kv[dst[u]], v[u]);
    } else if (b < BLK_A + BLK_B + BLK_C + BLK_D) {
        // ---- D: rope(k_pe[s]) broadcast -> res_kv slot0 [cols 128:192] ----
        unsigned base_i = (b - (BLK_A + BLK_B + BLK_C)) * 1024u + tid;
        #pragma unroll
        for (int u = 0; u < 4; u++) {
            unsigned i = base_i + u * 256u;
            unsigned row = i >> 4, c = i & 15;      // row = s*128 + h
            unsigned s = row >> 7, h = row & 127;
            int p = __ldg(&pos[s]);
            unsigned pc = (c < 8) ? c + 8 : c - 8;
            float sgn = (c < 8) ? -1.0f : 1.0f;

            const float4* kp = k_pe + s * (DROPE / 4);
            float4 x  = __ldg(&kp[c]);
            float4 xp = __ldg(&kp[pc]);
            float4 cc = __ldg((const float4*)(cos_t + p * DROPE) + c);
            float4 ss = __ldg((const float4*)(sin_t + p * DROPE) + c);

            unsigned dst = ((s << 8) + h) * VQK + 32 + c;   // rw = s*256 + h
            __stcs(&out_kv[dst], rope4(x, xp, cc, ss, sgn));
        }
    } else {
        // ---- E: zero fill -> res_kv slot1 [cols 128:192] ----
        unsigned base_i = (b - (BLK_A + BLK_B + BLK_C + BLK_D)) * 1024u + tid;
        const float4 z = make_float4(0.f, 0.f, 0.f, 0.f);
        #pragma unroll
        for (int u = 0; u < 4; u++) {
            unsigned i = base_i + u * 256u;
            unsigned row = i >> 4, c = i & 15;
            unsigned s = row >> 7, h = row & 127;
            unsigned dst = ((s << 8) + 128 + h) * VQK + 32 + c;
            __stcs(&out_kv[dst], z);
        }
    }
}

extern "C" void kernel_launch(void* const* d_in, const int* in_sizes, int n_in,
                              void* d_out, int out_size)
{
    const float4* q     = (const float4*)d_in[0];
    const float4* kv    = (const float4*)d_in[1];
    const float4* k_pe  = (const float4*)d_in[2];
    const float*  cos_t = (const float*)d_in[3];
    const float*  sin_t = (const float*)d_in[4];
    const int*    pos   = (const int*)d_in[5];

    float4* out_q  = (float4*)d_out;
    float4* out_kv = out_q + (long long)2048 * 128 * VQK;   // + 12,582,912

    fused_mla_rope_kernel<<<NBLOCKS, 256>>>(q, kv, k_pe, cos_t, sin_t, pos,
                                            out_q, out_kv);
}